// round 3
// baseline (speedup 1.0000x reference)
#include <cuda_runtime.h>

#define BATCH   16384
#define IN_DIM  1024
#define OUT_DIM 4096
#define TOPK    409

__device__ int g_flag;   // 1 => x.min() >= 0 (apply bipolar transform)

// ---------------------------------------------------------------------------
// packed fp32x2 helpers (Blackwell sm_100a+): 2 exact fp32 FMAs per issue
// ---------------------------------------------------------------------------
__device__ __forceinline__ void ffma2(unsigned long long& d,
                                      unsigned long long a,
                                      unsigned long long b) {
    asm("fma.rn.f32x2 %0, %1, %2, %0;" : "+l"(d) : "l"(a), "l"(b));
}
__device__ __forceinline__ unsigned long long pack2(float x, float y) {
    unsigned long long r;
    asm("mov.b64 %0, {%1, %2};" : "=l"(r) : "f"(x), "f"(y));
    return r;
}
__device__ __forceinline__ float2 unpack2(unsigned long long v) {
    float2 f;
    asm("mov.b64 {%0, %1}, %2;" : "=f"(f.x), "=f"(f.y) : "l"(v));
    return f;
}

// ---------------------------------------------------------------------------
// Kernel 0: reset flag (graph replays must be deterministic)
// ---------------------------------------------------------------------------
__global__ void init_flag_kernel() { g_flag = 1; }

// ---------------------------------------------------------------------------
// Kernel 1: any-negative scan over x (64 MB).
// ---------------------------------------------------------------------------
__global__ void scan_neg_kernel(const float4* __restrict__ x, int n4) {
    bool neg = false;
    for (int i = blockIdx.x * blockDim.x + threadIdx.x; i < n4;
         i += gridDim.x * blockDim.x) {
        float4 v = x[i];
        neg = neg || (v.x < 0.f) || (v.y < 0.f) || (v.z < 0.f) || (v.w < 0.f);
    }
    if (__syncthreads_or((int)neg)) {
        if (threadIdx.x == 0) g_flag = 0;   // racy same-value writes are fine
    }
}

// ---------------------------------------------------------------------------
// Kernel 2: SGEMM (NT): out[M,N] = X'[M,K] * W[N,K]^T  (exact fp32 via FFMA2)
// BM=BN=128, BK=8, 256 threads, 8x8 per-thread tile (as 8x4 packed pairs),
// smem double-buffered. Bipolar transform on A load when g_flag set.
// ---------------------------------------------------------------------------
__global__ __launch_bounds__(256, 2) void sgemm_nt_kernel(
    const float* __restrict__ A,   // X: [BATCH, IN_DIM]
    const float* __restrict__ B,   // W: [OUT_DIM, IN_DIM]
    float* __restrict__ C)         // proj: [BATCH, OUT_DIM]  (== d_out)
{
    __shared__ float As[2][8][128];
    __shared__ float Bs[2][8][128];

    const int tid  = threadIdx.x;
    const int brow = blockIdx.y * 128;
    const int bcol = blockIdx.x * 128;

    const bool bip = (g_flag != 0);

    // global->smem load mapping: one float4 of A and one of B per BK slab
    const int lrow = tid >> 1;          // 0..127 (tile row)
    const int lcol = (tid & 1) << 2;    // 0 or 4 (k offset)

    const float* Aptr = A + (size_t)(brow + lrow) * IN_DIM + lcol;
    const float* Bptr = B + (size_t)(bcol + lrow) * IN_DIM + lcol;

    // 16x16 thread grid of 8x8 tiles
    const int trow = (tid >> 4) << 3;   // 0..120
    const int tcol = (tid & 15) << 3;   // 0..120

    unsigned long long acc2[8][4];      // 8 rows x 4 packed col-pairs
#pragma unroll
    for (int i = 0; i < 8; i++)
#pragma unroll
        for (int j = 0; j < 4; j++) acc2[i][j] = 0ull;

    // ---- preload tile 0 ----
    float4 pa = *(const float4*)Aptr;
    float4 pb = *(const float4*)Bptr;
    if (bip) {
        pa.x = 2.f * pa.x - 1.f; pa.y = 2.f * pa.y - 1.f;
        pa.z = 2.f * pa.z - 1.f; pa.w = 2.f * pa.w - 1.f;
    }
    As[0][lcol + 0][lrow] = pa.x; As[0][lcol + 1][lrow] = pa.y;
    As[0][lcol + 2][lrow] = pa.z; As[0][lcol + 3][lrow] = pa.w;
    Bs[0][lcol + 0][lrow] = pb.x; Bs[0][lcol + 1][lrow] = pb.y;
    Bs[0][lcol + 2][lrow] = pb.z; Bs[0][lcol + 3][lrow] = pb.w;
    __syncthreads();

    int buf = 0;
    const int KT = IN_DIM / 8;          // 128
    for (int kt = 0; kt < KT; ++kt) {
        if (kt + 1 < KT) {              // prefetch next slab into registers
            pa = *(const float4*)(Aptr + (kt + 1) * 8);
            pb = *(const float4*)(Bptr + (kt + 1) * 8);
            if (bip) {
                pa.x = 2.f * pa.x - 1.f; pa.y = 2.f * pa.y - 1.f;
                pa.z = 2.f * pa.z - 1.f; pa.w = 2.f * pa.w - 1.f;
            }
        }
#pragma unroll
        for (int k = 0; k < 8; ++k) {
            // a values: 8 scalars, each duplicated into both f32x2 lanes
            float4 ta0 = *(const float4*)&As[buf][k][trow];
            float4 ta1 = *(const float4*)&As[buf][k][trow + 4];
            unsigned long long a2[8];
            a2[0] = pack2(ta0.x, ta0.x); a2[1] = pack2(ta0.y, ta0.y);
            a2[2] = pack2(ta0.z, ta0.z); a2[3] = pack2(ta0.w, ta0.w);
            a2[4] = pack2(ta1.x, ta1.x); a2[5] = pack2(ta1.y, ta1.y);
            a2[6] = pack2(ta1.z, ta1.z); a2[7] = pack2(ta1.w, ta1.w);
            // b pairs: adjacent floats are already a packed f32x2 in memory
            ulonglong2 tb0 = *(const ulonglong2*)&Bs[buf][k][tcol];
            ulonglong2 tb1 = *(const ulonglong2*)&Bs[buf][k][tcol + 4];
            unsigned long long b2[4] = { tb0.x, tb0.y, tb1.x, tb1.y };
#pragma unroll
            for (int i = 0; i < 8; i++)
#pragma unroll
                for (int j = 0; j < 4; j++)
                    ffma2(acc2[i][j], a2[i], b2[j]);
        }
        if (kt + 1 < KT) {
            const int nb = buf ^ 1;
            As[nb][lcol + 0][lrow] = pa.x; As[nb][lcol + 1][lrow] = pa.y;
            As[nb][lcol + 2][lrow] = pa.z; As[nb][lcol + 3][lrow] = pa.w;
            Bs[nb][lcol + 0][lrow] = pb.x; Bs[nb][lcol + 1][lrow] = pb.y;
            Bs[nb][lcol + 2][lrow] = pb.z; Bs[nb][lcol + 3][lrow] = pb.w;
            __syncthreads();
            buf = nb;
        }
    }

    // epilogue: write 8x8 tile (two float4 per row)
#pragma unroll
    for (int i = 0; i < 8; i++) {
        float2 c0 = unpack2(acc2[i][0]);
        float2 c1 = unpack2(acc2[i][1]);
        float2 c2 = unpack2(acc2[i][2]);
        float2 c3 = unpack2(acc2[i][3]);
        float* Crow = C + (size_t)(brow + trow + i) * OUT_DIM + bcol + tcol;
        *(float4*)(Crow)     = make_float4(c0.x, c0.y, c1.x, c1.y);
        *(float4*)(Crow + 4) = make_float4(c2.x, c2.y, c3.x, c3.y);
    }
}

// ---------------------------------------------------------------------------
// Kernel 3: per-row exact top-K threshold (32-bit radix select) + relu mask
//           + L2 normalize. One block (256 threads) per row. IN PLACE on out.
// ---------------------------------------------------------------------------
__device__ __forceinline__ unsigned f2k(float f) {
    unsigned u = __float_as_uint(f);
    return (u & 0x80000000u) ? ~u : (u | 0x80000000u);   // monotonic order map
}
__device__ __forceinline__ float k2f(unsigned k) {
    unsigned u = (k & 0x80000000u) ? (k ^ 0x80000000u) : ~k;
    return __uint_as_float(u);
}

__global__ __launch_bounds__(256) void topk_norm_kernel(float* __restrict__ out)
{
    __shared__ float    vals[OUT_DIM];       // 16 KB row cache
    __shared__ unsigned hist[256];
    __shared__ unsigned s_bin, s_rank;
    __shared__ float    s_inv;
    __shared__ float    warp_ss[8];

    const int tid = threadIdx.x;
    const size_t rowoff = (size_t)blockIdx.x * OUT_DIM;

    const float4* src = (const float4*)(out + rowoff);
    for (int i = tid; i < OUT_DIM / 4; i += 256)
        ((float4*)vals)[i] = src[i];
    __syncthreads();

    // radix select: exact bit pattern of the K-th largest value
    unsigned prefix = 0u, pmask = 0u, rank = TOPK;
    for (int shift = 24; shift >= 0; shift -= 8) {
        hist[tid] = 0u;
        __syncthreads();
        for (int i = tid; i < OUT_DIM; i += 256) {
            unsigned u = f2k(vals[i]);
            if ((u & pmask) == prefix)
                atomicAdd(&hist[(u >> shift) & 0xFFu], 1u);
        }
        __syncthreads();
        // inclusive suffix scan (hist[t] := sum_{j>=t} hist[j])
        for (int off = 1; off < 256; off <<= 1) {
            unsigned add = (tid + off < 256) ? hist[tid + off] : 0u;
            __syncthreads();
            hist[tid] += add;
            __syncthreads();
        }
        const unsigned cs = hist[tid];
        const unsigned nx = (tid < 255) ? hist[tid + 1] : 0u;
        if (cs >= rank && nx < rank) { s_bin = (unsigned)tid; s_rank = rank - nx; }
        __syncthreads();
        prefix |= s_bin << shift;
        pmask  |= 0xFFu << shift;
        rank    = s_rank;
        __syncthreads();
    }
    const float thr = k2f(prefix);

    // sum of squares of kept (relu + >= threshold) elements
    float ss = 0.f;
    for (int i = tid; i < OUT_DIM; i += 256) {
        float v = vals[i];
        float e = (v >= thr) ? fmaxf(v, 0.f) : 0.f;
        ss = fmaf(e, e, ss);
    }
#pragma unroll
    for (int o = 16; o; o >>= 1) ss += __shfl_xor_sync(0xFFFFFFFFu, ss, o);
    if ((tid & 31) == 0) warp_ss[tid >> 5] = ss;
    __syncthreads();
    if (tid == 0) {
        float t = 0.f;
#pragma unroll
        for (int i = 0; i < 8; i++) t += warp_ss[i];
        s_inv = 1.f / fmaxf(sqrtf(t), 1e-12f);
    }
    __syncthreads();
    const float inv = s_inv;

    float4* dst = (float4*)(out + rowoff);
    for (int i = tid; i < OUT_DIM / 4; i += 256) {
        float4 v = ((float4*)vals)[i];
        float4 o;
        o.x = ((v.x >= thr) ? fmaxf(v.x, 0.f) : 0.f) * inv;
        o.y = ((v.y >= thr) ? fmaxf(v.y, 0.f) : 0.f) * inv;
        o.z = ((v.z >= thr) ? fmaxf(v.z, 0.f) : 0.f) * inv;
        o.w = ((v.w >= thr) ? fmaxf(v.w, 0.f) : 0.f) * inv;
        dst[i] = o;
    }
}

// ---------------------------------------------------------------------------
extern "C" void kernel_launch(void* const* d_in, const int* in_sizes, int n_in,
                              void* d_out, int out_size)
{
    const float* x = (const float*)d_in[0];   // [16384, 1024]
    const float* w = (const float*)d_in[1];   // [4096, 1024]
    float* out = (float*)d_out;               // [16384, 4096]
    (void)in_sizes; (void)n_in; (void)out_size;

    init_flag_kernel<<<1, 1>>>();
    scan_neg_kernel<<<2048, 256>>>((const float4*)x, BATCH * IN_DIM / 4);

    dim3 ggrid(OUT_DIM / 128, BATCH / 128);   // 32 x 128 blocks
    sgemm_nt_kernel<<<ggrid, 256>>>(x, w, out);

    topk_norm_kernel<<<BATCH, 256>>>(out);
}

// round 7
// speedup vs baseline: 1.9101x; 1.9101x over previous
#include <cuda_runtime.h>
#include <cuda_bf16.h>
#include <cstdint>

#define BATCH   16384
#define IN_DIM  1024
#define OUT_DIM 4096
#define TOPK    409
#define EPS     1.5e-3f               // fixup window half-width (>> gemm err ~3e-5)
#define MAXCAND 128

#define BM 128
#define BN 128
#define BK 32
#define STAGES 3
#define NPASS 3
#define NCHUNK (NPASS * IN_DIM / BK)  // 96
#define RSTRIDE 80
#define TILE_BYTES (128 * RSTRIDE)
#define STAGE_BYTES (2 * TILE_BYTES)
#define SMEM_TOTAL (STAGES * STAGE_BYTES)

__device__ int g_flag;                                  // 1 => apply bipolar
__device__ __nv_bfloat16 g_xs[2ull * BATCH * IN_DIM];
__device__ __nv_bfloat16 g_ws[2ull * OUT_DIM * IN_DIM];
__constant__ int c_PA[NPASS] = {0, 0, 1};
__constant__ int c_PB[NPASS] = {0, 1, 0};

__device__ __forceinline__ uint32_t smem_u32(const void* p) {
    uint32_t a;
    asm("{ .reg .u64 t; cvta.to.shared.u64 t, %1; cvt.u32.u64 %0, t; }" : "=r"(a) : "l"(p));
    return a;
}
__device__ __forceinline__ void cp16(uint32_t dst, const void* src) {
    asm volatile("cp.async.cg.shared.global [%0], [%1], 16;" :: "r"(dst), "l"(src));
}
__device__ __forceinline__ uint32_t lds32(uint32_t addr) {
    uint32_t v;
    asm volatile("ld.shared.b32 %0, [%1];" : "=r"(v) : "r"(addr));
    return v;
}
__device__ __forceinline__ void mma_bf16(float& c0, float& c1, float& c2, float& c3,
                                         uint32_t a0, uint32_t a1, uint32_t a2, uint32_t a3,
                                         uint32_t b0, uint32_t b1) {
    asm volatile(
        "mma.sync.aligned.m16n8k16.row.col.f32.bf16.bf16.f32 "
        "{%0,%1,%2,%3}, {%4,%5,%6,%7}, {%8,%9}, {%0,%1,%2,%3};"
        : "+f"(c0), "+f"(c1), "+f"(c2), "+f"(c3)
        : "r"(a0), "r"(a1), "r"(a2), "r"(a3), "r"(b0), "r"(b1));
}

// ---------------------------------------------------------------------------
__global__ void init_flag_kernel() { g_flag = 1; }

__global__ void scan_neg_kernel(const float4* __restrict__ x, int n4) {
    bool neg = false;
    for (int i = blockIdx.x * blockDim.x + threadIdx.x; i < n4;
         i += gridDim.x * blockDim.x) {
        float4 v = x[i];
        neg = neg || (v.x < 0.f) || (v.y < 0.f) || (v.z < 0.f) || (v.w < 0.f);
    }
    if (__syncthreads_or((int)neg)) {
        if (threadIdx.x == 0) g_flag = 0;
    }
}

// ---------------------------------------------------------------------------
__device__ __forceinline__ void split2(float f, __nv_bfloat16& h, __nv_bfloat16& m) {
    h = __float2bfloat16(f);
    m = __float2bfloat16(f - __bfloat162float(h));
}

__global__ void convert_x_kernel(const float2* __restrict__ x) {
    const bool bip = (g_flag != 0);
    const size_t PL = (size_t)BATCH * IN_DIM;
    __nv_bfloat162* p0 = (__nv_bfloat162*)(g_xs);
    __nv_bfloat162* p1 = (__nv_bfloat162*)(g_xs + PL);
    int n2 = (int)(PL / 2);
    for (int i = blockIdx.x * blockDim.x + threadIdx.x; i < n2;
         i += gridDim.x * blockDim.x) {
        float2 v = x[i];
        if (bip) { v.x = 2.f * v.x - 1.f; v.y = 2.f * v.y - 1.f; }
        __nv_bfloat16 hx, mx, hy, my;
        split2(v.x, hx, mx);
        split2(v.y, hy, my);
        p0[i] = __nv_bfloat162(hx, hy);
        p1[i] = __nv_bfloat162(mx, my);
    }
}

__global__ void convert_w_kernel(const float2* __restrict__ w) {
    const size_t PL = (size_t)OUT_DIM * IN_DIM;
    __nv_bfloat162* p0 = (__nv_bfloat162*)(g_ws);
    __nv_bfloat162* p1 = (__nv_bfloat162*)(g_ws + PL);
    int n2 = (int)(PL / 2);
    for (int i = blockIdx.x * blockDim.x + threadIdx.x; i < n2;
         i += gridDim.x * blockDim.x) {
        float2 v = w[i];
        __nv_bfloat16 hx, mx, hy, my;
        split2(v.x, hx, mx);
        split2(v.y, hy, my);
        p0[i] = __nv_bfloat162(hx, hy);
        p1[i] = __nv_bfloat162(mx, my);
    }
}

// ---------------------------------------------------------------------------
// mma.sync bf16 GEMM, 3-pass split accumulated in registers (K' = 3072).
// ---------------------------------------------------------------------------
__device__ __forceinline__ void fill_stage(int chunk, uint32_t sbase, int brow,
                                           int bcol, int tid) {
    const int p  = chunk / (IN_DIM / BK);
    const int kc = (chunk % (IN_DIM / BK)) * BK;
    const int st = chunk % STAGES;
    const __nv_bfloat16* xa = g_xs + (size_t)c_PA[p] * BATCH * IN_DIM;
    const __nv_bfloat16* wb = g_ws + (size_t)c_PB[p] * OUT_DIM * IN_DIM;
    const uint32_t abase = sbase + st * STAGE_BYTES;
    const uint32_t bbase = abase + TILE_BYTES;

#pragma unroll
    for (int i = 0; i < 2; i++) {
        int idx = tid + i * 256;
        int row = idx >> 2, c = idx & 3;
        cp16(abase + row * RSTRIDE + c * 16,
             xa + (size_t)(brow + row) * IN_DIM + kc + c * 8);
        cp16(bbase + row * RSTRIDE + c * 16,
             wb + (size_t)(bcol + row) * IN_DIM + kc + c * 8);
    }
    asm volatile("cp.async.commit_group;" ::: "memory");
}

__global__ __launch_bounds__(256, 2) void gemm_mma_kernel(float* __restrict__ C) {
    extern __shared__ __align__(128) char smem[];
    const uint32_t sbase = smem_u32(smem);
    const int tid  = threadIdx.x;
    const int wid  = tid >> 5;
    const int lane = tid & 31;
    const int wm   = wid >> 2;
    const int wn   = wid & 3;
    const int brow = blockIdx.y * BM;
    const int bcol = blockIdx.x * BN;

    float acc[4][4][4];
#pragma unroll
    for (int mi = 0; mi < 4; mi++)
#pragma unroll
        for (int ni = 0; ni < 4; ni++)
#pragma unroll
            for (int r = 0; r < 4; r++) acc[mi][ni][r] = 0.f;

    fill_stage(0, sbase, brow, bcol, tid);
    fill_stage(1, sbase, brow, bcol, tid);

    const int qrow = lane >> 2;
    const int kb0  = (lane & 3) * 4;

    for (int kt = 0; kt < NCHUNK; ++kt) {
        if (kt + 2 < NCHUNK) asm volatile("cp.async.wait_group 1;" ::: "memory");
        else                 asm volatile("cp.async.wait_group 0;" ::: "memory");
        __syncthreads();

        if (kt + 2 < NCHUNK) fill_stage(kt + 2, sbase, brow, bcol, tid);

        const uint32_t abase = sbase + (kt % STAGES) * STAGE_BYTES;
        const uint32_t bbase = abase + TILE_BYTES;

#pragma unroll
        for (int step = 0; step < 2; ++step) {
            const uint32_t kb = kb0 + step * 32;
            uint32_t a[4][4], b[4][2];
#pragma unroll
            for (int mi = 0; mi < 4; mi++) {
                const uint32_t r0 = abase + (wm * 64 + mi * 16 + qrow) * RSTRIDE + kb;
                a[mi][0] = lds32(r0);
                a[mi][1] = lds32(r0 + 8 * RSTRIDE);
                a[mi][2] = lds32(r0 + 16);
                a[mi][3] = lds32(r0 + 8 * RSTRIDE + 16);
            }
#pragma unroll
            for (int ni = 0; ni < 4; ni++) {
                const uint32_t n0 = bbase + (wn * 32 + ni * 8 + qrow) * RSTRIDE + kb;
                b[ni][0] = lds32(n0);
                b[ni][1] = lds32(n0 + 16);
            }
#pragma unroll
            for (int mi = 0; mi < 4; mi++)
#pragma unroll
                for (int ni = 0; ni < 4; ni++)
                    mma_bf16(acc[mi][ni][0], acc[mi][ni][1],
                             acc[mi][ni][2], acc[mi][ni][3],
                             a[mi][0], a[mi][1], a[mi][2], a[mi][3],
                             b[ni][0], b[ni][1]);
        }
        __syncthreads();
    }

    const int crow = brow + wm * 64 + qrow;
    const int ccol = bcol + wn * 32 + 2 * (lane & 3);
#pragma unroll
    for (int mi = 0; mi < 4; mi++) {
#pragma unroll
        for (int ni = 0; ni < 4; ni++) {
            float* p0 = C + (size_t)(crow + mi * 16) * OUT_DIM + ccol + ni * 8;
            float* p1 = p0 + 8 * OUT_DIM;
            *(float2*)p0 = make_float2(acc[mi][ni][0], acc[mi][ni][1]);
            *(float2*)p1 = make_float2(acc[mi][ni][2], acc[mi][ni][3]);
        }
    }
}

// ---------------------------------------------------------------------------
// top-K with exact-fp32 boundary fixup + relu + L2 normalize (in place)
// ---------------------------------------------------------------------------
__device__ __forceinline__ unsigned f2k(float f) {
    unsigned u = __float_as_uint(f);
    return (u & 0x80000000u) ? ~u : (u | 0x80000000u);
}
__device__ __forceinline__ float k2f(unsigned k) {
    unsigned u = (k & 0x80000000u) ? (k ^ 0x80000000u) : ~k;
    return __uint_as_float(u);
}

__global__ __launch_bounds__(256) void topk_fix_kernel(
    float* __restrict__ out, const float* __restrict__ x, const float* __restrict__ w)
{
    __shared__ float    vals[OUT_DIM];        // 16 KB row cache (approx proj)
    __shared__ float    xrow[IN_DIM];         // 4 KB exact (bipolar-applied) x
    __shared__ unsigned char inwin[OUT_DIM];  // 4 KB window flags
    __shared__ unsigned hist[256];
    __shared__ int      s_cidx[MAXCAND];
    __shared__ float    s_cex[MAXCAND];
    __shared__ int      s_ncand, s_nhi;
    __shared__ unsigned s_bin, s_rank;
    __shared__ float    s_thrx, s_inv;
    __shared__ float    warp_red[8];

    const int tid  = threadIdx.x;
    const int lane = tid & 31;
    const int wid  = tid >> 5;
    const size_t rowoff = (size_t)blockIdx.x * OUT_DIM;

    // load approx projections + exact x row
    const float4* src = (const float4*)(out + rowoff);
    for (int i = tid; i < OUT_DIM / 4; i += 256)
        ((float4*)vals)[i] = src[i];
    {
        const bool bip = (g_flag != 0);
        const float4* xs = (const float4*)(x + (size_t)blockIdx.x * IN_DIM);
        for (int i = tid; i < IN_DIM / 4; i += 256) {
            float4 v = xs[i];
            if (bip) {
                v.x = 2.f * v.x - 1.f; v.y = 2.f * v.y - 1.f;
                v.z = 2.f * v.z - 1.f; v.w = 2.f * v.w - 1.f;
            }
            ((float4*)xrow)[i] = v;
        }
    }
    if (tid == 0) { s_ncand = 0; s_nhi = 0; }
    __syncthreads();

    // ---- approx radix select: K-th largest approx value ----
    unsigned prefix = 0u, pmask = 0u, rank = TOPK;
    for (int shift = 24; shift >= 0; shift -= 8) {
        hist[tid] = 0u;
        __syncthreads();
        for (int i = tid; i < OUT_DIM; i += 256) {
            unsigned u = f2k(vals[i]);
            if ((u & pmask) == prefix)
                atomicAdd(&hist[(u >> shift) & 0xFFu], 1u);
        }
        __syncthreads();
        for (int off = 1; off < 256; off <<= 1) {
            unsigned add = (tid + off < 256) ? hist[tid + off] : 0u;
            __syncthreads();
            hist[tid] += add;
            __syncthreads();
        }
        const unsigned cs = hist[tid];
        const unsigned nx = (tid < 255) ? hist[tid + 1] : 0u;
        if (cs >= rank && nx < rank) { s_bin = (unsigned)tid; s_rank = rank - nx; }
        __syncthreads();
        prefix |= s_bin << shift;
        pmask  |= 0xFFu << shift;
        rank    = s_rank;
        __syncthreads();
    }
    const float thr = k2f(prefix);

    // ---- collect boundary candidates; count certain-keeps ----
    int local_hi = 0;
    for (int i = tid; i < OUT_DIM; i += 256) {
        float v = vals[i];
        unsigned char f = 0;
        if (fabsf(v - thr) <= EPS) {
            int p = atomicAdd(&s_ncand, 1);
            if (p < MAXCAND) { s_cidx[p] = i; f = 1; }
            else if (v > thr) local_hi++;      // overflow fallback (≈ never)
        } else if (v > thr) {
            local_hi++;
        }
        inwin[i] = f;
    }
    atomicAdd(&s_nhi, local_hi);
    __syncthreads();

    const int nc = min(s_ncand, MAXCAND);
    const int kwin = TOPK - s_nhi;            // how many to keep from window (>=1)

    // ---- exact fp32 dots for candidates (one warp per candidate) ----
    for (int c = wid; c < nc; c += 8) {
        const float* wr = w + (size_t)s_cidx[c] * IN_DIM;
        float s = 0.f;
        for (int k = lane; k < IN_DIM; k += 32)
            s = fmaf(xrow[k], wr[k], s);
#pragma unroll
        for (int o = 16; o; o >>= 1) s += __shfl_xor_sync(0xFFFFFFFFu, s, o);
        if (lane == 0) { s_cex[c] = s; vals[s_cidx[c]] = s; }
    }
    __syncthreads();

    // ---- exact threshold among candidates: kwin-th largest ----
    float tmin = 3.402823466e+38f;
    for (int c = tid; c < nc; c += 256) {
        float e = s_cex[c];
        int gt = 0;
        for (int j = 0; j < nc; j++) gt += (s_cex[j] > e);
        if (gt <= kwin - 1) tmin = fminf(tmin, e);
    }
#pragma unroll
    for (int o = 16; o; o >>= 1) tmin = fminf(tmin, __shfl_xor_sync(0xFFFFFFFFu, tmin, o));
    if (lane == 0) warp_red[wid] = tmin;
    __syncthreads();
    if (tid == 0) {
        float t = warp_red[0];
#pragma unroll
        for (int i = 1; i < 8; i++) t = fminf(t, warp_red[i]);
        s_thrx = t;
    }
    __syncthreads();
    const float thrx = s_thrx;

    // ---- sum of squares of kept relu values ----
    float ss = 0.f;
    for (int i = tid; i < OUT_DIM; i += 256) {
        float v = vals[i];
        bool keep = inwin[i] ? (v >= thrx) : (v > thr);
        float e = keep ? fmaxf(v, 0.f) : 0.f;
        ss = fmaf(e, e, ss);
    }
#pragma unroll
    for (int o = 16; o; o >>= 1) ss += __shfl_xor_sync(0xFFFFFFFFu, ss, o);
    if (lane == 0) warp_red[wid] = ss;
    __syncthreads();
    if (tid == 0) {
        float t = 0.f;
#pragma unroll
        for (int i = 0; i < 8; i++) t += warp_red[i];
        s_inv = 1.f / fmaxf(sqrtf(t), 1e-12f);
    }
    __syncthreads();
    const float inv = s_inv;

    float4* dst = (float4*)(out + rowoff);
    for (int g = tid; g < OUT_DIM / 4; g += 256) {
        const int i = g * 4;
        float4 o;
        {
            float v = vals[i];
            o.x = ((inwin[i] ? (v >= thrx) : (v > thr)) ? fmaxf(v, 0.f) : 0.f) * inv;
        }
        {
            float v = vals[i + 1];
            o.y = ((inwin[i + 1] ? (v >= thrx) : (v > thr)) ? fmaxf(v, 0.f) : 0.f) * inv;
        }
        {
            float v = vals[i + 2];
            o.z = ((inwin[i + 2] ? (v >= thrx) : (v > thr)) ? fmaxf(v, 0.f) : 0.f) * inv;
        }
        {
            float v = vals[i + 3];
            o.w = ((inwin[i + 3] ? (v >= thrx) : (v > thr)) ? fmaxf(v, 0.f) : 0.f) * inv;
        }
        dst[g] = o;
    }
}

// ---------------------------------------------------------------------------
extern "C" void kernel_launch(void* const* d_in, const int* in_sizes, int n_in,
                              void* d_out, int out_size)
{
    const float* x = (const float*)d_in[0];   // [16384, 1024]
    const float* w = (const float*)d_in[1];   // [4096, 1024]
    float* out = (float*)d_out;               // [16384, 4096]
    (void)in_sizes; (void)n_in; (void)out_size;

    cudaFuncSetAttribute(gemm_mma_kernel,
                         cudaFuncAttributeMaxDynamicSharedMemorySize, SMEM_TOTAL);

    init_flag_kernel<<<1, 1>>>();
    scan_neg_kernel<<<2048, 256>>>((const float4*)x, BATCH * IN_DIM / 4);
    convert_w_kernel<<<4096, 256>>>((const float2*)w);
    convert_x_kernel<<<16384, 256>>>((const float2*)x);

    dim3 ggrid(OUT_DIM / BN, BATCH / BM);     // 32 x 128 CTAs
    gemm_mma_kernel<<<ggrid, 256, SMEM_TOTAL>>>(out);

    topk_fix_kernel<<<BATCH, 256>>>(out, x, w);
}